// round 15
// baseline (speedup 1.0000x reference)
#include <cuda_runtime.h>
#include <cuda_bf16.h>
#include <math.h>
#include <cstdint>

#define B_ 4
#define T_ 8
#define C_ 128
#define HW_ 9216
#define NBT 32
#define TILEP 32
#define NTILE 288

typedef unsigned long long ull;
typedef unsigned int u32;

__device__ __forceinline__ ull pack2(float a, float b) {
    ull r; asm("mov.b64 %0,{%1,%2};" : "=l"(r) : "f"(a), "f"(b)); return r;
}
__device__ __forceinline__ void unpack2(ull v, float& a, float& b) {
    asm("mov.b64 {%0,%1},%2;" : "=f"(a), "=f"(b) : "l"(v));
}
__device__ __forceinline__ ull fma2(ull a, ull b, ull c) {
    ull d; asm("fma.rn.f32x2 %0,%1,%2,%3;" : "=l"(d) : "l"(a), "l"(b), "l"(c)); return d;
}
__device__ __forceinline__ ull mul2(ull a, ull b) {
    ull d; asm("mul.rn.f32x2 %0,%1,%2;" : "=l"(d) : "l"(a), "l"(b)); return d;
}

// hi/lo bf16 split of two floats -> two b32
__device__ __forceinline__ void split_pair(float v0, float v1, u32& h, u32& l) {
    __nv_bfloat16 h0 = __float2bfloat16(v0);
    __nv_bfloat16 h1 = __float2bfloat16(v1);
    float r0 = v0 - __bfloat162float(h0);
    float r1 = v1 - __bfloat162float(h1);
    __nv_bfloat162 hh; hh.x = h0; hh.y = h1;
    __nv_bfloat162 llv; llv.x = __float2bfloat16(r0); llv.y = __float2bfloat16(r1);
    h = *(u32*)&hh; l = *(u32*)&llv;
}

// m16n8k16 row.col f32.bf16.bf16.f32
__device__ __forceinline__ void mma16816(float c[4], const u32 a[4], const u32 b[2]) {
    asm volatile("mma.sync.aligned.m16n8k16.row.col.f32.bf16.bf16.f32 "
                 "{%0,%1,%2,%3},{%4,%5,%6,%7},{%8,%9},{%0,%1,%2,%3};"
                 : "+f"(c[0]), "+f"(c[1]), "+f"(c[2]), "+f"(c[3])
                 : "r"(a[0]), "r"(a[1]), "r"(a[2]), "r"(a[3]), "r"(b[0]), "r"(b[1]));
}

// deterministic scratch
__device__ float g_psum[NBT * C_];
__device__ float g_psq [NBT * C_];
__device__ float g_A[NBT * C_];
__device__ float g_Bc[NBT * C_];
// fragment-order weights: [mat][plane hi/lo][w16][ks][lane][4 u32]
__device__ u32 g_Wpk[4 * 16384];

// ---------------- Kernel 1: per-(bt,c) channel reduction ----------------
__global__ __launch_bounds__(256) void reduce_kernel(const float* __restrict__ x,
                                                     const float* __restrict__ pos) {
    int bt = blockIdx.x >> 7;
    int c  = blockIdx.x & 127;
    int t  = bt & (T_ - 1);
    const float4* x4 = (const float4*)(x + ((size_t)bt * C_ + c) * HW_);
    float pv = pos[t * C_ + c];
    float s = 0.f, sq = 0.f;
#pragma unroll
    for (int i = 0; i < 9; i++) {          // 9*256 = 2304 float4 = 9216 floats
        float4 v = x4[i * 256 + threadIdx.x];
        float a0 = v.x + pv, a1 = v.y + pv, a2 = v.z + pv, a3 = v.w + pv;
        s  += (a0 + a1) + (a2 + a3);
        sq += (a0 * a0 + a1 * a1) + (a2 * a2 + a3 * a3);
    }
    __shared__ float ss[8], ssq[8];
#pragma unroll
    for (int o = 16; o; o >>= 1) {
        s  += __shfl_down_sync(0xFFFFFFFFu, s, o);
        sq += __shfl_down_sync(0xFFFFFFFFu, sq, o);
    }
    int w = threadIdx.x >> 5;
    if ((threadIdx.x & 31) == 0) { ss[w] = s; ssq[w] = sq; }
    __syncthreads();
    if (threadIdx.x == 0) {
        float S = 0.f, SQ = 0.f;
#pragma unroll
        for (int i = 0; i < 8; i++) { S += ss[i]; SQ += ssq[i]; }
        g_psum[bt * C_ + c] = S;
        g_psq [bt * C_ + c] = SQ;
    }
}

// ---------------- Kernel 2: fused finalize + weight prep ----------------
__global__ __launch_bounds__(256) void prep_kernel(const float* __restrict__ pos,
                                                   const float* __restrict__ nw,
                                                   const float* __restrict__ nb,
                                                   const float* __restrict__ qkv_w,
                                                   const float* __restrict__ proj_w) {
    int tid = threadIdx.x;
    if (blockIdx.x == 32) {
        // finalize mean/rstd -> affine A,B
        __shared__ float sm[NBT], sr[NBT];
        if (tid < NBT) {
            float S = 0.f, SQ = 0.f;
            for (int i = 0; i < C_; i++) { S += g_psum[tid * C_ + i]; SQ += g_psq[tid * C_ + i]; }
            const float invN = 1.0f / (float)(C_ * HW_);
            float mean = S * invN;
            float var = SQ * invN - mean * mean;
            sm[tid] = mean;
            sr[tid] = rsqrtf(var + 1e-5f);
        }
        __syncthreads();
        for (int idx = tid; idx < NBT * C_; idx += 256) {
            int bt = idx >> 7, c = idx & 127, t = bt & (T_ - 1);
            float a = sr[bt] * nw[c];
            g_A[idx] = a;
            g_Bc[idx] = (pos[t * C_ + c] - sm[bt]) * a + nb[c];
        }
        return;
    }
    // weight prep in fragment order (blocks 0..31)
    int i = blockIdx.x * 256 + tid;   // 0..8191
    int mat  = i >> 11;
    int rem  = i & 2047;
    int w16  = rem >> 8;
    int ks   = (rem >> 5) & 7;
    int lane = rem & 31;
    int g = lane >> 2, t = lane & 3;
    int r0 = w16 * 16 + g, r1 = r0 + 8;
    int kp0 = 8 * ks + t, kp1 = kp0 + 4;
    const float sc = 0.17677669529663687f;

    auto fetch = [&](int r, int c) -> float {
        if (mat == 0) return qkv_w[r * 128 + c];
        if (mat == 1) return qkv_w[(128 + c) * 128 + r] * sc;   // WkT (scaled)
        if (mat == 2) return qkv_w[(256 + r) * 128 + c];
        return proj_w[r * 128 + c];
    };

    u32 H[4], L[4];
    split_pair(fetch(r0, 2 * kp0), fetch(r0, 2 * kp0 + 1), H[0], L[0]);
    split_pair(fetch(r1, 2 * kp0), fetch(r1, 2 * kp0 + 1), H[1], L[1]);
    split_pair(fetch(r0, 2 * kp1), fetch(r0, 2 * kp1 + 1), H[2], L[2]);
    split_pair(fetch(r1, 2 * kp1), fetch(r1, 2 * kp1 + 1), H[3], L[3]);

    int base = mat * 16384 + ((w16 * 8 + ks) * 32 + lane) * 4;
    *(uint4*)(g_Wpk + base)        = make_uint4(H[0], H[1], H[2], H[3]);
    *(uint4*)(g_Wpk + 8192 + base) = make_uint4(L[0], L[1], L[2], L[3]);
}

// ---------------- Kernel 3: fused main ----------------
#define P4 34               // uint4 pitch: conflict-free fragment reads
// float-unit layout:
// [0,4352)        slot0 tile; sP ping-pong overlays [0,4096)
// [4352,8704)     slot1 tile (Q output); E tiles h=0..3 at 4352 + h*4352
// [8704,25088)    sUP (8192 ull fp32-pairs)
// [25088,27136)   affine AB
#define SM_S1   4352
#define SM_UP   8704
#define SM_AB   25088
#define SMEM_FLOATS 27136
#define SMEM_BYTES (SMEM_FLOATS * 4)   // 108544

// compensated GEMM slice: fragment-order weights + uint4 row-pair B tiles
__device__ __forceinline__ void gemm_mma(const u32* __restrict__ Whi, const u32* __restrict__ Wlo,
                                         const uint4* __restrict__ Bt,
                                         int w16, int lane, int g, int t,
                                         int ks0, int ksn, float acc[4][4]) {
    const u32* wp = Whi + ((w16 * 8 + ks0) * 32 + lane) * 4;
    const u32* wq = Wlo + ((w16 * 8 + ks0) * 32 + lane) * 4;
    const uint4* brow = Bt + (ks0 * 4 + t) * P4 + g;
#pragma unroll
    for (int ki = 0; ki < ksn; ki++) {
        uint4 aH4 = *(const uint4*)wp;
        uint4 aL4 = *(const uint4*)wq;
        u32 aH[4] = {aH4.x, aH4.y, aH4.z, aH4.w};
        u32 aL[4] = {aL4.x, aL4.y, aL4.z, aL4.w};
#pragma unroll
        for (int nt = 0; nt < 4; nt++) {
            uint4 bq = brow[8 * nt];
            u32 bh[2] = {bq.x, bq.z};
            u32 bl[2] = {bq.y, bq.w};
            mma16816(acc[nt], aH, bh);
            mma16816(acc[nt], aL, bh);
            mma16816(acc[nt], aH, bl);
        }
        wp += 128; wq += 128; brow += 4 * P4;
    }
}

// shuffle-pair direct store of D fragment into a uint4 row-pair B-tile
__device__ __forceinline__ void frag_store_tile(const float acc[4][4], int g, int t,
                                                uint4* Bt, int w16) {
    int ri = w16 * 4 + (g >> 1);
#pragma unroll
    for (int nt = 0; nt < 4; nt++) {
        float o0 = __shfl_xor_sync(0xFFFFFFFFu, acc[nt][0], 4);
        float o1 = __shfl_xor_sync(0xFFFFFFFFu, acc[nt][1], 4);
        float o2 = __shfl_xor_sync(0xFFFFFFFFu, acc[nt][2], 4);
        float o3 = __shfl_xor_sync(0xFFFFFFFFu, acc[nt][3], 4);
        int col = 8 * nt + 2 * t + (g & 1);
        float v0, v1, u0, u1;
        if ((g & 1) == 0) { v0 = acc[nt][0]; v1 = o0; u0 = acc[nt][2]; u1 = o2; }
        else              { v0 = o1; v1 = acc[nt][1]; u0 = o3; u1 = acc[nt][3]; }
        u32 vh, vl, uh, ulw;
        split_pair(v0, v1, vh, vl);
        split_pair(u0, u1, uh, ulw);
        Bt[ri * P4 + col] = make_uint4(vh, vl, uh, ulw);
    }
}

// shuffle-pair direct store of D fragment into fp32-pair ull array (U)
__device__ __forceinline__ void frag_store_up(const float acc[4][4], int g, int t,
                                              ull* UP, int rowBase) {
    int c2 = g >> 1;
#pragma unroll
    for (int nt = 0; nt < 4; nt++) {
        float o0 = __shfl_xor_sync(0xFFFFFFFFu, acc[nt][0], 4);
        float o1 = __shfl_xor_sync(0xFFFFFFFFu, acc[nt][1], 4);
        float o2 = __shfl_xor_sync(0xFFFFFFFFu, acc[nt][2], 4);
        float o3 = __shfl_xor_sync(0xFFFFFFFFu, acc[nt][3], 4);
        int col = 8 * nt + 2 * t + (g & 1);
        ull lo, hi;
        if ((g & 1) == 0) { lo = pack2(acc[nt][0], o0); hi = pack2(acc[nt][2], o2); }
        else              { lo = pack2(o1, acc[nt][1]); hi = pack2(o3, acc[nt][3]); }
        UP[(rowBase + c2) * 32 + col]     = lo;
        UP[(rowBase + c2 + 4) * 32 + col] = hi;
    }
}

__global__ __launch_bounds__(256, 2) void main_kernel(const float* __restrict__ x,
                                                      float* __restrict__ out) {
    extern __shared__ float sm[];
    uint4* sT0 = (uint4*)sm;
    uint4* sS1 = (uint4*)(sm + SM_S1);
    ull* UPa  = (ull*)(sm + SM_UP);
    float* sAB = sm + SM_AB;

    int b    = blockIdx.x / NTILE;
    int tile = blockIdx.x % NTILE;
    int hw0  = tile * TILEP;
    int tid  = threadIdx.x;
    int wid  = tid >> 5, lane = tid & 31;
    int g    = lane >> 2, t = lane & 3;
    int cld  = wid;
    int pld  = lane;
    int c0   = cld * 16;

    // stage affine tables
    for (int idx = tid; idx < 1024; idx += 256) {
        sAB[idx]        = g_A [b * 1024 + idx];
        sAB[1024 + idx] = g_Bc[b * 1024 + idx];
    }
    // raw x7 + t0 prefetch
    float xn[16], xr[16];
    {
        const float* xb7 = x + (size_t)(b * T_ + 7) * C_ * HW_;
        const float* xb0 = x + (size_t)(b * T_) * C_ * HW_;
#pragma unroll
        for (int j = 0; j < 16; j++) xn[j] = xb7[(c0 + j) * HW_ + hw0 + pld];
#pragma unroll
        for (int j = 0; j < 16; j++) xr[j] = xb0[(c0 + j) * HW_ + hw0 + pld];
    }
    __syncthreads();

    // normalize x7; pack slot0 B tile (row-pair uint4)
    {
        const float* As = sAB + 7 * 128;
        const float* Bs = sAB + 1024 + 7 * 128;
#pragma unroll
        for (int j = 0; j < 16; j++) xn[j] = xn[j] * As[c0 + j] + Bs[c0 + j];
#pragma unroll
        for (int k = 0; k < 4; k++) {
            u32 h0, l0, h1, l1;
            split_pair(xn[2 * k], xn[2 * k + 1], h0, l0);
            split_pair(xn[2 * (k + 4)], xn[2 * (k + 4) + 1], h1, l1);
            sT0[(cld * 4 + k) * P4 + pld] = make_uint4(h0, l0, h1, l1);
        }
    }
    __syncthreads();

    // ---- Phase Q: Wq @ XN7 -> slot1 tile ----
    {
        float acc[4][4] = {};
        gemm_mma(g_Wpk, g_Wpk + 8192, sT0, wid, lane, g, t, 0, 8, acc);
        frag_store_tile(acc, g, t, sS1, wid);
    }
    __syncthreads();

    // ---- Phase U: per head h (ks {2h,2h+1}) -> sUP fp32-pairs ----
    {
        const u32* Whi = g_Wpk + 16384;
        const u32* Wlo = g_Wpk + 16384 + 8192;
#pragma unroll
        for (int h = 0; h < 4; h++) {
            float acc[4][4] = {};
            gemm_mma(Whi, Wlo, sS1, wid, lane, g, t, 2 * h, 2, acc);
            frag_store_up(acc, g, t, UPa, h * 64 + 8 * wid);
        }
    }
    __syncthreads();

    // ---- paired online softmax + xbar: timestep pairs (7,0),(1,2),(3,4),(5,6) ----
    ull xnA[8], xnB[8];
#pragma unroll
    for (int k = 0; k < 8; k++) xnA[k] = pack2(xn[2 * k], xn[2 * k + 1]);

    ull xbarP[4][8];
#pragma unroll
    for (int h = 0; h < 4; h++)
#pragma unroll
        for (int k = 0; k < 8; k++) xbarP[h][k] = 0ull;
    float m_run[4] = {-1e30f, -1e30f, -1e30f, -1e30f};
    float s_run[4] = {0.f, 0.f, 0.f, 0.f};

    const ull* upb = UPa + (8 * cld) * 32 + pld;   // + h*2048 + k*32

#pragma unroll
    for (int p = 0; p < 4; p++) {
        int sa = (p == 0) ? 7 : (2 * p - 1);
        int sb = 2 * p;
        float* sPbA = sm + (p & 1) * 2048;
        float* sPbB = sPbA + 1024;

        if (p == 0) {
            const float* As = sAB;
            const float* Bs = sAB + 1024;
#pragma unroll
            for (int k = 0; k < 8; k++) {
                float a0 = xr[2 * k] * As[c0 + 2 * k] + Bs[c0 + 2 * k];
                float a1 = xr[2 * k + 1] * As[c0 + 2 * k + 1] + Bs[c0 + 2 * k + 1];
                xnB[k] = pack2(a0, a1);
            }
        } else {
            float rb[16];
            const float* xbS = x + (size_t)(b * T_ + sb) * C_ * HW_;
#pragma unroll
            for (int j = 0; j < 16; j++) rb[j] = xbS[(c0 + j) * HW_ + hw0 + pld];
            const float* Asa = sAB + sa * 128;
            const float* Bsa = sAB + 1024 + sa * 128;
#pragma unroll
            for (int k = 0; k < 8; k++) {
                float a0 = xr[2 * k] * Asa[c0 + 2 * k] + Bsa[c0 + 2 * k];
                float a1 = xr[2 * k + 1] * Asa[c0 + 2 * k + 1] + Bsa[c0 + 2 * k + 1];
                xnA[k] = pack2(a0, a1);
            }
            const float* Asb = sAB + sb * 128;
            const float* Bsb = sAB + 1024 + sb * 128;
#pragma unroll
            for (int k = 0; k < 8; k++) {
                float a0 = rb[2 * k] * Asb[c0 + 2 * k] + Bsb[c0 + 2 * k];
                float a1 = rb[2 * k + 1] * Asb[c0 + 2 * k + 1] + Bsb[c0 + 2 * k + 1];
                xnB[k] = pack2(a0, a1);
            }
        }
        if (p < 3) {
            const float* xbN = x + (size_t)(b * T_ + 2 * p + 1) * C_ * HW_;
#pragma unroll
            for (int j = 0; j < 16; j++) xr[j] = xbN[(c0 + j) * HW_ + hw0 + pld];
        }

        // single U pass, both timesteps
        ull lgA[4] = {0ull, 0ull, 0ull, 0ull};
        ull lgB[4] = {0ull, 0ull, 0ull, 0ull};
#pragma unroll
        for (int k = 0; k < 8; k++) {
            ull xa = xnA[k], xb2 = xnB[k];
            ull u0 = upb[0 * 2048 + k * 32];
            ull u1 = upb[1 * 2048 + k * 32];
            ull u2 = upb[2 * 2048 + k * 32];
            ull u3 = upb[3 * 2048 + k * 32];
            lgA[0] = fma2(xa, u0, lgA[0]);  lgB[0] = fma2(xb2, u0, lgB[0]);
            lgA[1] = fma2(xa, u1, lgA[1]);  lgB[1] = fma2(xb2, u1, lgB[1]);
            lgA[2] = fma2(xa, u2, lgA[2]);  lgB[2] = fma2(xb2, u2, lgB[2]);
            lgA[3] = fma2(xa, u3, lgA[3]);  lgB[3] = fma2(xb2, u3, lgB[3]);
        }
        float4 pA, pBv;
        { float lo, hi;
          unpack2(lgA[0], lo, hi); pA.x = lo + hi;
          unpack2(lgA[1], lo, hi); pA.y = lo + hi;
          unpack2(lgA[2], lo, hi); pA.z = lo + hi;
          unpack2(lgA[3], lo, hi); pA.w = lo + hi;
          unpack2(lgB[0], lo, hi); pBv.x = lo + hi;
          unpack2(lgB[1], lo, hi); pBv.y = lo + hi;
          unpack2(lgB[2], lo, hi); pBv.z = lo + hi;
          unpack2(lgB[3], lo, hi); pBv.w = lo + hi; }
        *(float4*)(sPbA + (cld * 32 + pld) * 4) = pA;
        *(float4*)(sPbB + (cld * 32 + pld) * 4) = pBv;
        __syncthreads();
        float LA[4] = {0.f, 0.f, 0.f, 0.f};
        float LB[4] = {0.f, 0.f, 0.f, 0.f};
#pragma unroll
        for (int k = 0; k < 8; k++) {
            float4 vA = *(const float4*)(sPbA + (k * 32 + pld) * 4);
            float4 vB = *(const float4*)(sPbB + (k * 32 + pld) * 4);
            LA[0] += vA.x; LA[1] += vA.y; LA[2] += vA.z; LA[3] += vA.w;
            LB[0] += vB.x; LB[1] += vB.y; LB[2] += vB.z; LB[3] += vB.w;
        }
        // no trailing sync (ping-pong)

        // fused double online-softmax update
#pragma unroll
        for (int h = 0; h < 4; h++) {
            float m1 = fmaxf(m_run[h], LA[h]);
            float cA = __expf(m_run[h] - m1);
            float eA = __expf(LA[h] - m1);
            float m2 = fmaxf(m1, LB[h]);
            float cB = __expf(m1 - m2);
            float eB = __expf(LB[h] - m2);
            s_run[h] = (s_run[h] * cA + eA) * cB + eB;
            m_run[h] = m2;
            float cc = cA * cB, ea = eA * cB;
            ull ccP = pack2(cc, cc), eaP = pack2(ea, ea), ebP = pack2(eB, eB);
#pragma unroll
            for (int k = 0; k < 8; k++)
                xbarP[h][k] = fma2(ebP, xnB[k], fma2(eaP, xnA[k], mul2(ccP, xbarP[h][k])));
        }
    }
    __syncthreads();   // sUP reads + sP ping-pong done

    // ---- Phase E single pass: pack all 4 head tiles, all 8 warps compute ----
    {
#pragma unroll
        for (int h = 0; h < 4; h++) {
            float inv = 1.0f / s_run[h];
            ull iP = pack2(inv, inv);
            uint4* Et = (uint4*)(sm + SM_S1 + h * 4352);
#pragma unroll
            for (int k = 0; k < 4; k++) {
                float v0, v1, u0, u1;
                unpack2(mul2(iP, xbarP[h][k]), v0, v1);
                unpack2(mul2(iP, xbarP[h][k + 4]), u0, u1);
                u32 h0, l0, h1, l1;
                split_pair(v0, v1, h0, l0);
                split_pair(u0, u1, h1, l1);
                Et[(cld * 4 + k) * P4 + pld] = make_uint4(h0, l0, h1, l1);
            }
        }
        __syncthreads();
        const u32* Whi = g_Wpk + 2 * 16384;
        const u32* Wlo = g_Wpk + 2 * 16384 + 8192;
        int h = wid >> 1;
        uint4* Et = (uint4*)(sm + SM_S1 + h * 4352);
        float acc[4][4] = {};
        gemm_mma(Whi, Wlo, Et, wid, lane, g, t, 0, 8, acc);
        frag_store_tile(acc, g, t, sT0, wid);
    }
    __syncthreads();

    // ---- Phase F: y = proj @ Out -> gmem direct ----
    {
        const u32* Whi = g_Wpk + 3 * 16384;
        const u32* Wlo = g_Wpk + 3 * 16384 + 8192;
        float acc[4][4] = {};
        gemm_mma(Whi, Wlo, sT0, wid, lane, g, t, 0, 8, acc);
        float* o0 = out + ((size_t)b * C_ + 16 * wid + g) * HW_ + hw0;
        float* o8 = out + ((size_t)b * C_ + 16 * wid + g + 8) * HW_ + hw0;
#pragma unroll
        for (int nt = 0; nt < 4; nt++) {
            int px = 8 * nt + 2 * t;
            *(float2*)(o0 + px) = make_float2(acc[nt][0], acc[nt][1]);
            *(float2*)(o8 + px) = make_float2(acc[nt][2], acc[nt][3]);
        }
    }
}

extern "C" void kernel_launch(void* const* d_in, const int* in_sizes, int n_in,
                              void* d_out, int out_size) {
    const float* x    = (const float*)d_in[0];
    const float* pos  = (const float*)d_in[1];
    const float* nw   = (const float*)d_in[2];
    const float* nb   = (const float*)d_in[3];
    const float* qkvw = (const float*)d_in[4];
    const float* pw   = (const float*)d_in[5];
    float* out = (float*)d_out;

    reduce_kernel<<<NBT * C_, 256>>>(x, pos);
    prep_kernel<<<33, 256>>>(pos, nw, nb, qkvw, pw);
    cudaFuncSetAttribute(main_kernel, cudaFuncAttributeMaxDynamicSharedMemorySize, SMEM_BYTES);
    main_kernel<<<B_ * NTILE, 256, SMEM_BYTES>>>(x, out);
}

// round 16
// speedup vs baseline: 1.0418x; 1.0418x over previous
#include <cuda_runtime.h>
#include <cuda_bf16.h>
#include <math.h>
#include <cstdint>

#define B_ 4
#define T_ 8
#define C_ 128
#define HW_ 9216
#define NBT 32
#define NCHUNK 72
#define CHUNK 16384
#define TILEP 32
#define NTILE 288

typedef unsigned long long ull;
typedef unsigned int u32;

__device__ __forceinline__ ull pack2(float a, float b) {
    ull r; asm("mov.b64 %0,{%1,%2};" : "=l"(r) : "f"(a), "f"(b)); return r;
}
__device__ __forceinline__ void unpack2(ull v, float& a, float& b) {
    asm("mov.b64 {%0,%1},%2;" : "=f"(a), "=f"(b) : "l"(v));
}
__device__ __forceinline__ ull fma2(ull a, ull b, ull c) {
    ull d; asm("fma.rn.f32x2 %0,%1,%2,%3;" : "=l"(d) : "l"(a), "l"(b), "l"(c)); return d;
}
__device__ __forceinline__ ull mul2(ull a, ull b) {
    ull d; asm("mul.rn.f32x2 %0,%1,%2;" : "=l"(d) : "l"(a), "l"(b)); return d;
}

// hi/lo bf16 split of two floats -> two b32
__device__ __forceinline__ void split_pair(float v0, float v1, u32& h, u32& l) {
    __nv_bfloat16 h0 = __float2bfloat16(v0);
    __nv_bfloat16 h1 = __float2bfloat16(v1);
    float r0 = v0 - __bfloat162float(h0);
    float r1 = v1 - __bfloat162float(h1);
    __nv_bfloat162 hh; hh.x = h0; hh.y = h1;
    __nv_bfloat162 llv; llv.x = __float2bfloat16(r0); llv.y = __float2bfloat16(r1);
    h = *(u32*)&hh; l = *(u32*)&llv;
}

// m16n8k16 row.col f32.bf16.bf16.f32
__device__ __forceinline__ void mma16816(float c[4], const u32 a[4], const u32 b[2]) {
    asm volatile("mma.sync.aligned.m16n8k16.row.col.f32.bf16.bf16.f32 "
                 "{%0,%1,%2,%3},{%4,%5,%6,%7},{%8,%9},{%0,%1,%2,%3};"
                 : "+f"(c[0]), "+f"(c[1]), "+f"(c[2]), "+f"(c[3])
                 : "r"(a[0]), "r"(a[1]), "r"(a[2]), "r"(a[3]), "r"(b[0]), "r"(b[1]));
}

// deterministic scratch
__device__ float g_psum[NBT * NCHUNK];
__device__ float g_psq [NBT * NCHUNK];
__device__ float g_A[NBT * C_];
__device__ float g_Bc[NBT * C_];
__device__ int   g_cnt;
// fragment-order weights: [mat][plane hi/lo][w16][ks][lane][4 u32]
__device__ u32 g_Wpk[4 * 16384];

// ---------------- Kernel 1: reduce + weight-prep + last-block finalize ----------------
__global__ __launch_bounds__(256) void front_kernel(const float* __restrict__ x,
                                                    const float* __restrict__ pos,
                                                    const float* __restrict__ nw,
                                                    const float* __restrict__ nb,
                                                    const float* __restrict__ qkv_w,
                                                    const float* __restrict__ proj_w) {
    int tid = threadIdx.x;
    if (blockIdx.x >= NBT * NCHUNK) {
        // ---- weight prep in fragment order (32 blocks) ----
        int i = (blockIdx.x - NBT * NCHUNK) * 256 + tid;   // 0..8191
        int mat  = i >> 11;
        int rem  = i & 2047;
        int w16  = rem >> 8;
        int ks   = (rem >> 5) & 7;
        int lane = rem & 31;
        int g = lane >> 2, t = lane & 3;
        int r0 = w16 * 16 + g, r1 = r0 + 8;
        int kp0 = 8 * ks + t, kp1 = kp0 + 4;
        const float sc = 0.17677669529663687f;

        auto fetch = [&](int r, int c) -> float {
            if (mat == 0) return qkv_w[r * 128 + c];
            if (mat == 1) return qkv_w[(128 + c) * 128 + r] * sc;   // WkT (scaled)
            if (mat == 2) return qkv_w[(256 + r) * 128 + c];
            return proj_w[r * 128 + c];
        };

        u32 H[4], L[4];
        split_pair(fetch(r0, 2 * kp0), fetch(r0, 2 * kp0 + 1), H[0], L[0]);
        split_pair(fetch(r1, 2 * kp0), fetch(r1, 2 * kp0 + 1), H[1], L[1]);
        split_pair(fetch(r0, 2 * kp1), fetch(r0, 2 * kp1 + 1), H[2], L[2]);
        split_pair(fetch(r1, 2 * kp1), fetch(r1, 2 * kp1 + 1), H[3], L[3]);

        int base = mat * 16384 + ((w16 * 8 + ks) * 32 + lane) * 4;
        *(uint4*)(g_Wpk + base)        = make_uint4(H[0], H[1], H[2], H[3]);
        *(uint4*)(g_Wpk + 8192 + base) = make_uint4(L[0], L[1], L[2], L[3]);
        return;
    }

    // ---- chunk reduce (blocks 0..2303) ----
    int bt    = blockIdx.x / NCHUNK;
    int chunk = blockIdx.x % NCHUNK;
    int t     = bt & (T_ - 1);
    const float4* x4 = (const float4*)(x + (size_t)bt * C_ * HW_);
    int base4 = chunk * (CHUNK / 4);
    float s = 0.f, sq = 0.f;
#pragma unroll
    for (int i = 0; i < 16; i++) {
        int e4 = base4 + i * 256 + tid;
        int c = e4 / 2304;
        float pv = pos[t * C_ + c];
        float4 v = x4[e4];
        float a0 = v.x + pv, a1 = v.y + pv, a2 = v.z + pv, a3 = v.w + pv;
        s += (a0 + a1) + (a2 + a3);
        sq += (a0 * a0 + a1 * a1) + (a2 * a2 + a3 * a3);
    }
    __shared__ float ss[8], ssq[8];
    __shared__ int sLast;
#pragma unroll
    for (int o = 16; o; o >>= 1) {
        s += __shfl_down_sync(0xFFFFFFFFu, s, o);
        sq += __shfl_down_sync(0xFFFFFFFFu, sq, o);
    }
    int w = tid >> 5;
    if ((tid & 31) == 0) { ss[w] = s; ssq[w] = sq; }
    __syncthreads();
    if (tid == 0) {
        float S = 0.f, SQ = 0.f;
#pragma unroll
        for (int i = 0; i < 8; i++) { S += ss[i]; SQ += ssq[i]; }
        g_psum[bt * NCHUNK + chunk] = S;
        g_psq [bt * NCHUNK + chunk] = SQ;
        __threadfence();
        int prev = atomicAdd(&g_cnt, 1);
        sLast = (prev == NBT * NCHUNK - 1) ? 1 : 0;
    }
    __syncthreads();
    if (!sLast) return;

    // ---- finalize (executed by the last reduce block only; deterministic values) ----
    __shared__ float sm_[NBT], sr_[NBT];
    if (tid < NBT) {
        float S = 0.f, SQ = 0.f;
        for (int i = 0; i < NCHUNK; i++) { S += g_psum[tid * NCHUNK + i]; SQ += g_psq[tid * NCHUNK + i]; }
        const float invN = 1.0f / (float)(C_ * HW_);
        float mean = S * invN;
        float var = SQ * invN - mean * mean;
        sm_[tid] = mean;
        sr_[tid] = rsqrtf(var + 1e-5f);
    }
    __syncthreads();
    for (int idx = tid; idx < NBT * C_; idx += 256) {
        int bt2 = idx >> 7, c = idx & 127, t2 = bt2 & (T_ - 1);
        float a = sr_[bt2] * nw[c];
        g_A[idx] = a;
        g_Bc[idx] = (pos[t2 * C_ + c] - sm_[bt2]) * a + nb[c];
    }
    if (tid == 0) g_cnt = 0;   // reset for next graph replay
}

// ---------------- Kernel 3: fused main (byte-identical to round 14) ----------------
#define P4 34               // uint4 pitch: conflict-free fragment reads
#define SM_S1   4352
#define SM_UP   8704
#define SM_AB   25088
#define SMEM_FLOATS 27136
#define SMEM_BYTES (SMEM_FLOATS * 4)   // 108544

__device__ __forceinline__ void gemm_mma(const u32* __restrict__ Whi, const u32* __restrict__ Wlo,
                                         const uint4* __restrict__ Bt,
                                         int w16, int lane, int g, int t,
                                         int ks0, int ksn, float acc[4][4]) {
#pragma unroll
    for (int ki = 0; ki < ksn; ki++) {
        int ks = ks0 + ki;
        int fi = ((w16 * 8 + ks) * 32 + lane) * 4;
        uint4 aH4 = *(const uint4*)(Whi + fi);
        uint4 aL4 = *(const uint4*)(Wlo + fi);
        u32 aH[4] = {aH4.x, aH4.y, aH4.z, aH4.w};
        u32 aL[4] = {aL4.x, aL4.y, aL4.z, aL4.w};
        const uint4* brow = Bt + (ks * 4 + t) * P4 + g;
#pragma unroll
        for (int nt = 0; nt < 4; nt++) {
            uint4 bq = brow[8 * nt];
            u32 bh[2] = {bq.x, bq.z};
            u32 bl[2] = {bq.y, bq.w};
            mma16816(acc[nt], aH, bh);
            mma16816(acc[nt], aL, bh);
            mma16816(acc[nt], aH, bl);
        }
    }
}

__device__ __forceinline__ void frag_store_tile(const float acc[4][4], int g, int t,
                                                uint4* Bt, int w16) {
    int ri = w16 * 4 + (g >> 1);
#pragma unroll
    for (int nt = 0; nt < 4; nt++) {
        float o0 = __shfl_xor_sync(0xFFFFFFFFu, acc[nt][0], 4);
        float o1 = __shfl_xor_sync(0xFFFFFFFFu, acc[nt][1], 4);
        float o2 = __shfl_xor_sync(0xFFFFFFFFu, acc[nt][2], 4);
        float o3 = __shfl_xor_sync(0xFFFFFFFFu, acc[nt][3], 4);
        int col = 8 * nt + 2 * t + (g & 1);
        float v0, v1, u0, u1;
        if ((g & 1) == 0) { v0 = acc[nt][0]; v1 = o0; u0 = acc[nt][2]; u1 = o2; }
        else              { v0 = o1; v1 = acc[nt][1]; u0 = o3; u1 = acc[nt][3]; }
        u32 vh, vl, uh, ulw;
        split_pair(v0, v1, vh, vl);
        split_pair(u0, u1, uh, ulw);
        Bt[ri * P4 + col] = make_uint4(vh, vl, uh, ulw);
    }
}

__device__ __forceinline__ void frag_store_up(const float acc[4][4], int g, int t,
                                              ull* UP, int rowBase) {
    int c2 = g >> 1;
#pragma unroll
    for (int nt = 0; nt < 4; nt++) {
        float o0 = __shfl_xor_sync(0xFFFFFFFFu, acc[nt][0], 4);
        float o1 = __shfl_xor_sync(0xFFFFFFFFu, acc[nt][1], 4);
        float o2 = __shfl_xor_sync(0xFFFFFFFFu, acc[nt][2], 4);
        float o3 = __shfl_xor_sync(0xFFFFFFFFu, acc[nt][3], 4);
        int col = 8 * nt + 2 * t + (g & 1);
        ull lo, hi;
        if ((g & 1) == 0) { lo = pack2(acc[nt][0], o0); hi = pack2(acc[nt][2], o2); }
        else              { lo = pack2(o1, acc[nt][1]); hi = pack2(o3, acc[nt][3]); }
        UP[(rowBase + c2) * 32 + col]     = lo;
        UP[(rowBase + c2 + 4) * 32 + col] = hi;
    }
}

__global__ __launch_bounds__(256, 2) void main_kernel(const float* __restrict__ x,
                                                      float* __restrict__ out) {
    extern __shared__ float sm[];
    uint4* sT0 = (uint4*)sm;
    uint4* sS1 = (uint4*)(sm + SM_S1);
    ull* UPa  = (ull*)(sm + SM_UP);
    float* sAB = sm + SM_AB;

    int b    = blockIdx.x / NTILE;
    int tile = blockIdx.x % NTILE;
    int hw0  = tile * TILEP;
    int tid  = threadIdx.x;
    int wid  = tid >> 5, lane = tid & 31;
    int g    = lane >> 2, t = lane & 3;
    int cld  = wid;
    int pld  = lane;
    int c0   = cld * 16;

    for (int idx = tid; idx < 1024; idx += 256) {
        sAB[idx]        = g_A [b * 1024 + idx];
        sAB[1024 + idx] = g_Bc[b * 1024 + idx];
    }
    float xn[16], xr[16];
    {
        const float* xb7 = x + (size_t)(b * T_ + 7) * C_ * HW_;
        const float* xb0 = x + (size_t)(b * T_) * C_ * HW_;
#pragma unroll
        for (int j = 0; j < 16; j++) xn[j] = xb7[(c0 + j) * HW_ + hw0 + pld];
#pragma unroll
        for (int j = 0; j < 16; j++) xr[j] = xb0[(c0 + j) * HW_ + hw0 + pld];
    }
    __syncthreads();

    {
        const float* As = sAB + 7 * 128;
        const float* Bs = sAB + 1024 + 7 * 128;
#pragma unroll
        for (int j = 0; j < 16; j++) xn[j] = xn[j] * As[c0 + j] + Bs[c0 + j];
#pragma unroll
        for (int k = 0; k < 4; k++) {
            u32 h0, l0, h1, l1;
            split_pair(xn[2 * k], xn[2 * k + 1], h0, l0);
            split_pair(xn[2 * (k + 4)], xn[2 * (k + 4) + 1], h1, l1);
            sT0[(cld * 4 + k) * P4 + pld] = make_uint4(h0, l0, h1, l1);
        }
    }
    __syncthreads();

    {
        float acc[4][4] = {};
        gemm_mma(g_Wpk, g_Wpk + 8192, sT0, wid, lane, g, t, 0, 8, acc);
        frag_store_tile(acc, g, t, sS1, wid);
    }
    __syncthreads();

    {
        const u32* Whi = g_Wpk + 16384;
        const u32* Wlo = g_Wpk + 16384 + 8192;
#pragma unroll
        for (int h = 0; h < 4; h++) {
            float acc[4][4] = {};
            gemm_mma(Whi, Wlo, sS1, wid, lane, g, t, 2 * h, 2, acc);
            frag_store_up(acc, g, t, UPa, h * 64 + 8 * wid);
        }
    }
    __syncthreads();

    ull xnA[8], xnB[8];
#pragma unroll
    for (int k = 0; k < 8; k++) xnA[k] = pack2(xn[2 * k], xn[2 * k + 1]);

    ull xbarP[4][8];
#pragma unroll
    for (int h = 0; h < 4; h++)
#pragma unroll
        for (int k = 0; k < 8; k++) xbarP[h][k] = 0ull;
    float m_run[4] = {-1e30f, -1e30f, -1e30f, -1e30f};
    float s_run[4] = {0.f, 0.f, 0.f, 0.f};

    const ull* upb = UPa + (8 * cld) * 32 + pld;

#pragma unroll
    for (int p = 0; p < 4; p++) {
        int sa = (p == 0) ? 7 : (2 * p - 1);
        int sb = 2 * p;
        float* sPbA = sm + (p & 1) * 2048;
        float* sPbB = sPbA + 1024;

        if (p == 0) {
            const float* As = sAB;
            const float* Bs = sAB + 1024;
#pragma unroll
            for (int k = 0; k < 8; k++) {
                float a0 = xr[2 * k] * As[c0 + 2 * k] + Bs[c0 + 2 * k];
                float a1 = xr[2 * k + 1] * As[c0 + 2 * k + 1] + Bs[c0 + 2 * k + 1];
                xnB[k] = pack2(a0, a1);
            }
        } else {
            float rb[16];
            const float* xbS = x + (size_t)(b * T_ + sb) * C_ * HW_;
#pragma unroll
            for (int j = 0; j < 16; j++) rb[j] = xbS[(c0 + j) * HW_ + hw0 + pld];
            const float* Asa = sAB + sa * 128;
            const float* Bsa = sAB + 1024 + sa * 128;
#pragma unroll
            for (int k = 0; k < 8; k++) {
                float a0 = xr[2 * k] * Asa[c0 + 2 * k] + Bsa[c0 + 2 * k];
                float a1 = xr[2 * k + 1] * Asa[c0 + 2 * k + 1] + Bsa[c0 + 2 * k + 1];
                xnA[k] = pack2(a0, a1);
            }
            const float* Asb = sAB + sb * 128;
            const float* Bsb = sAB + 1024 + sb * 128;
#pragma unroll
            for (int k = 0; k < 8; k++) {
                float a0 = rb[2 * k] * Asb[c0 + 2 * k] + Bsb[c0 + 2 * k];
                float a1 = rb[2 * k + 1] * Asb[c0 + 2 * k + 1] + Bsb[c0 + 2 * k + 1];
                xnB[k] = pack2(a0, a1);
            }
        }
        if (p < 3) {
            const float* xbN = x + (size_t)(b * T_ + 2 * p + 1) * C_ * HW_;
#pragma unroll
            for (int j = 0; j < 16; j++) xr[j] = xbN[(c0 + j) * HW_ + hw0 + pld];
        }

        ull lgA[4] = {0ull, 0ull, 0ull, 0ull};
        ull lgB[4] = {0ull, 0ull, 0ull, 0ull};
#pragma unroll
        for (int k = 0; k < 8; k++) {
            ull xa = xnA[k], xb2 = xnB[k];
            ull u0 = upb[0 * 2048 + k * 32];
            ull u1 = upb[1 * 2048 + k * 32];
            ull u2 = upb[2 * 2048 + k * 32];
            ull u3 = upb[3 * 2048 + k * 32];
            lgA[0] = fma2(xa, u0, lgA[0]);  lgB[0] = fma2(xb2, u0, lgB[0]);
            lgA[1] = fma2(xa, u1, lgA[1]);  lgB[1] = fma2(xb2, u1, lgB[1]);
            lgA[2] = fma2(xa, u2, lgA[2]);  lgB[2] = fma2(xb2, u2, lgB[2]);
            lgA[3] = fma2(xa, u3, lgA[3]);  lgB[3] = fma2(xb2, u3, lgB[3]);
        }
        float4 pA, pBv;
        { float lo, hi;
          unpack2(lgA[0], lo, hi); pA.x = lo + hi;
          unpack2(lgA[1], lo, hi); pA.y = lo + hi;
          unpack2(lgA[2], lo, hi); pA.z = lo + hi;
          unpack2(lgA[3], lo, hi); pA.w = lo + hi;
          unpack2(lgB[0], lo, hi); pBv.x = lo + hi;
          unpack2(lgB[1], lo, hi); pBv.y = lo + hi;
          unpack2(lgB[2], lo, hi); pBv.z = lo + hi;
          unpack2(lgB[3], lo, hi); pBv.w = lo + hi; }
        *(float4*)(sPbA + (cld * 32 + pld) * 4) = pA;
        *(float4*)(sPbB + (cld * 32 + pld) * 4) = pBv;
        __syncthreads();
        float LA[4] = {0.f, 0.f, 0.f, 0.f};
        float LB[4] = {0.f, 0.f, 0.f, 0.f};
#pragma unroll
        for (int k = 0; k < 8; k++) {
            float4 vA = *(const float4*)(sPbA + (k * 32 + pld) * 4);
            float4 vB = *(const float4*)(sPbB + (k * 32 + pld) * 4);
            LA[0] += vA.x; LA[1] += vA.y; LA[2] += vA.z; LA[3] += vA.w;
            LB[0] += vB.x; LB[1] += vB.y; LB[2] += vB.z; LB[3] += vB.w;
        }

#pragma unroll
        for (int h = 0; h < 4; h++) {
            float m1 = fmaxf(m_run[h], LA[h]);
            float cA = __expf(m_run[h] - m1);
            float eA = __expf(LA[h] - m1);
            float m2 = fmaxf(m1, LB[h]);
            float cB = __expf(m1 - m2);
            float eB = __expf(LB[h] - m2);
            s_run[h] = (s_run[h] * cA + eA) * cB + eB;
            m_run[h] = m2;
            float cc = cA * cB, ea = eA * cB;
            ull ccP = pack2(cc, cc), eaP = pack2(ea, ea), ebP = pack2(eB, eB);
#pragma unroll
            for (int k = 0; k < 8; k++)
                xbarP[h][k] = fma2(ebP, xnB[k], fma2(eaP, xnA[k], mul2(ccP, xbarP[h][k])));
        }
    }
    __syncthreads();

    {
#pragma unroll
        for (int h = 0; h < 4; h++) {
            float inv = 1.0f / s_run[h];
            ull iP = pack2(inv, inv);
            uint4* Et = (uint4*)(sm + SM_S1 + h * 4352);
#pragma unroll
            for (int k = 0; k < 4; k++) {
                float v0, v1, u0, u1;
                unpack2(mul2(iP, xbarP[h][k]), v0, v1);
                unpack2(mul2(iP, xbarP[h][k + 4]), u0, u1);
                u32 h0, l0, h1, l1;
                split_pair(v0, v1, h0, l0);
                split_pair(u0, u1, h1, l1);
                Et[(cld * 4 + k) * P4 + pld] = make_uint4(h0, l0, h1, l1);
            }
        }
        __syncthreads();
        const u32* Whi = g_Wpk + 2 * 16384;
        const u32* Wlo = g_Wpk + 2 * 16384 + 8192;
        int h = wid >> 1;
        uint4* Et = (uint4*)(sm + SM_S1 + h * 4352);
        float acc[4][4] = {};
        gemm_mma(Whi, Wlo, Et, wid, lane, g, t, 0, 8, acc);
        frag_store_tile(acc, g, t, sT0, wid);
    }
    __syncthreads();

    {
        const u32* Whi = g_Wpk + 3 * 16384;
        const u32* Wlo = g_Wpk + 3 * 16384 + 8192;
        float acc[4][4] = {};
        gemm_mma(Whi, Wlo, sT0, wid, lane, g, t, 0, 8, acc);
        float* o0 = out + ((size_t)b * C_ + 16 * wid + g) * HW_ + hw0;
        float* o8 = out + ((size_t)b * C_ + 16 * wid + g + 8) * HW_ + hw0;
#pragma unroll
        for (int nt = 0; nt < 4; nt++) {
            int px = 8 * nt + 2 * t;
            *(float2*)(o0 + px) = make_float2(acc[nt][0], acc[nt][1]);
            *(float2*)(o8 + px) = make_float2(acc[nt][2], acc[nt][3]);
        }
    }
}

extern "C" void kernel_launch(void* const* d_in, const int* in_sizes, int n_in,
                              void* d_out, int out_size) {
    const float* x    = (const float*)d_in[0];
    const float* pos  = (const float*)d_in[1];
    const float* nw   = (const float*)d_in[2];
    const float* nb   = (const float*)d_in[3];
    const float* qkvw = (const float*)d_in[4];
    const float* pw   = (const float*)d_in[5];
    float* out = (float*)d_out;

    front_kernel<<<NBT * NCHUNK + 32, 256>>>(x, pos, nw, nb, qkvw, pw);
    cudaFuncSetAttribute(main_kernel, cudaFuncAttributeMaxDynamicSharedMemorySize, SMEM_BYTES);
    main_kernel<<<B_ * NTILE, 256, SMEM_BYTES>>>(x, out);
}